// round 1
// baseline (speedup 1.0000x reference)
#include <cuda_runtime.h>
#include <cuda_bf16.h>

// RippleNet: H=2, B=2048, M=64, D=16, N_ENT=500000, N_REL=32
// inputs (metadata order): items[B] i32, heads[H,B,M] i32, relations[H,B,M] i32,
//                          tails[H,B,M] i32, ent_emb[N_ENT,16] f32, rel_emb[32,16,16] f32
// output: predicts[B] f32

#define H_ 2
#define B_ 2048
#define M_ 64
#define D_ 16
#define NREL_ 32

__global__ __launch_bounds__(128) void ripple_kernel(
    const int* __restrict__ items,
    const int* __restrict__ heads,
    const int* __restrict__ rels,
    const int* __restrict__ tails,
    const float* __restrict__ ent,
    const float* __restrict__ rel,
    float* __restrict__ out)
{
    const int b   = blockIdx.x;
    const int tid = threadIdx.x;

    __shared__ float item_s[D_];
    __shared__ float q[NREL_ * 17];   // stride 17: avoid 32-way bank conflicts on random ridx
    __shared__ float redmax[4];
    __shared__ float rede[4];
    __shared__ float redes[4];

    // ---- load item embedding (one row, 64B) ----
    if (tid < D_) item_s[tid] = ent[(size_t)items[b] * D_ + tid];
    __syncthreads();

    // ---- issue index loads + embedding gathers early (hide latency) ----
    const int h = tid >> 6;           // hop
    const int base = h * (B_ * M_) + b * M_ + (tid & 63);
    const int hidx = heads[base];
    const int ridx = rels[base];
    const int tidx = tails[base];

    const float4* hp = (const float4*)(ent + (size_t)hidx * D_);
    const float4* tp = (const float4*)(ent + (size_t)tidx * D_);
    float4 hv0 = hp[0], hv1 = hp[1], hv2 = hp[2], hv3 = hp[3];
    float4 tv0 = tp[0], tv1 = tp[1], tv2 = tp[2], tv3 = tp[3];

    // ---- precompute q[r][j] = sum_i item[i] * R_r[i][j]  (R^T item, all 32 rels) ----
    // 512 outputs, 4 per thread; rel table (32KB) is L1-resident.
    #pragma unroll
    for (int o = tid; o < NREL_ * D_; o += 128) {
        const int r = o >> 4, j = o & 15;
        const float* Rp = rel + r * (D_ * D_) + j;
        float acc = 0.f;
        #pragma unroll
        for (int i = 0; i < D_; i++) acc = fmaf(item_s[i], Rp[i * D_], acc);
        q[r * 17 + j] = acc;
    }
    __syncthreads();

    // ---- per-(h,m) logit l = q[ridx] . head, and s = tail . item ----
    const float* qr = &q[ridx * 17];
    float l = 0.f;
    l = fmaf(qr[0],  hv0.x, l); l = fmaf(qr[1],  hv0.y, l);
    l = fmaf(qr[2],  hv0.z, l); l = fmaf(qr[3],  hv0.w, l);
    l = fmaf(qr[4],  hv1.x, l); l = fmaf(qr[5],  hv1.y, l);
    l = fmaf(qr[6],  hv1.z, l); l = fmaf(qr[7],  hv1.w, l);
    l = fmaf(qr[8],  hv2.x, l); l = fmaf(qr[9],  hv2.y, l);
    l = fmaf(qr[10], hv2.z, l); l = fmaf(qr[11], hv2.w, l);
    l = fmaf(qr[12], hv3.x, l); l = fmaf(qr[13], hv3.y, l);
    l = fmaf(qr[14], hv3.z, l); l = fmaf(qr[15], hv3.w, l);

    float s = 0.f;
    s = fmaf(item_s[0],  tv0.x, s); s = fmaf(item_s[1],  tv0.y, s);
    s = fmaf(item_s[2],  tv0.z, s); s = fmaf(item_s[3],  tv0.w, s);
    s = fmaf(item_s[4],  tv1.x, s); s = fmaf(item_s[5],  tv1.y, s);
    s = fmaf(item_s[6],  tv1.z, s); s = fmaf(item_s[7],  tv1.w, s);
    s = fmaf(item_s[8],  tv2.x, s); s = fmaf(item_s[9],  tv2.y, s);
    s = fmaf(item_s[10], tv2.z, s); s = fmaf(item_s[11], tv2.w, s);
    s = fmaf(item_s[12], tv3.x, s); s = fmaf(item_s[13], tv3.y, s);
    s = fmaf(item_s[14], tv3.z, s); s = fmaf(item_s[15], tv3.w, s);

    // ---- softmax over m (64 threads = 2 warps per hop h) ----
    const int w = tid >> 5;
    float wm = l;
    #pragma unroll
    for (int off = 16; off; off >>= 1)
        wm = fmaxf(wm, __shfl_xor_sync(0xffffffffu, wm, off));
    if ((tid & 31) == 0) redmax[w] = wm;
    __syncthreads();
    const float gmax = fmaxf(redmax[2 * h], redmax[2 * h + 1]);

    const float e  = __expf(l - gmax);
    float se  = e;
    float ses = e * s;
    #pragma unroll
    for (int off = 16; off; off >>= 1) {
        se  += __shfl_xor_sync(0xffffffffu, se,  off);
        ses += __shfl_xor_sync(0xffffffffu, ses, off);
    }
    if ((tid & 31) == 0) { rede[w] = se; redes[w] = ses; }
    __syncthreads();

    if (tid == 0) {
        const float r0 = (redes[0] + redes[1]) / (rede[0] + rede[1]);
        const float r1 = (redes[2] + redes[3]) / (rede[2] + rede[3]);
        const float x  = r0 + r1;
        out[b] = 1.f / (1.f + __expf(-x));
    }
}

extern "C" void kernel_launch(void* const* d_in, const int* in_sizes, int n_in,
                              void* d_out, int out_size) {
    const int*   items = (const int*)  d_in[0];
    const int*   heads = (const int*)  d_in[1];
    const int*   rels  = (const int*)  d_in[2];
    const int*   tails = (const int*)  d_in[3];
    const float* ent   = (const float*)d_in[4];
    const float* rel   = (const float*)d_in[5];
    float* out = (float*)d_out;

    ripple_kernel<<<B_, 128>>>(items, heads, rels, tails, ent, rel, out);
}